// round 1
// baseline (speedup 1.0000x reference)
#include <cuda_runtime.h>

#define BB 1024
#define DD 64
#define FF 8
#define ZZ 72          // D + F
#define HH 256
#define TT 50
#define TUU 128
#define NSUB 4
#define ROWS 8         // batch rows per CTA
#define CTAS (BB/ROWS) // 128
#define NTHREADS 256

typedef unsigned long long u64;

__device__ __forceinline__ u64 fma2(u64 a, u64 b, u64 c) {
    u64 d;
    asm("fma.rn.f32x2 %0, %1, %2, %3;" : "=l"(d) : "l"(a), "l"(b), "l"(c));
    return d;
}
__device__ __forceinline__ u64 pack2(float lo, float hi) {
    u64 d;
    asm("mov.b64 %0, {%1, %2};" : "=l"(d) : "f"(lo), "f"(hi));
    return d;
}
__device__ __forceinline__ float2 unpack2(u64 v) {
    float lo, hi;
    asm("mov.b64 {%0, %1}, %2;" : "=f"(lo), "=f"(hi) : "l"(v));
    return make_float2(lo, hi);
}

// tanh(x) = 1 - 2/(exp(2x)+1), via ex2.approx (rel err ~2^-22) + rcp.approx.
// Saturates correctly to +-1 for large |x|. Abs error ~1e-6: far below the
// 1e-3 harness threshold even after ODE error amplification.
__device__ __forceinline__ float fast_tanh(float x) {
    float e, r;
    asm("ex2.approx.f32 %0, %1;" : "=f"(e) : "f"(x * 2.8853900817779268f)); // 2*log2(e)
    asm("rcp.approx.f32 %0, %1;" : "=f"(r) : "f"(e + 1.0f));
    return fmaf(-2.0f, r, 1.0f);
}

// Shared memory layout (floats):
//   ubuf : ROWS*TUU*FF = 8192
//   zbuf : ROWS*ZZ     = 576
//   hbuf : ROWS*HH     = 2048
//   part : ROWS*HH     = 2048
//   te   : 64 (T=50 padded)
//   tu   : 128
#define SMEM_FLOATS (8192 + 576 + 2048 + 2048 + 64 + 128)

__global__ void __launch_bounds__(NTHREADS, 1)
node_kernel(const float* __restrict__ x0g, const float* __restrict__ te_g,
            const float* __restrict__ tu_g, const float* __restrict__ u_g,
            const float* __restrict__ W1g, const float* __restrict__ b1g,
            const float* __restrict__ W2g, const float* __restrict__ b2g,
            float* __restrict__ out)
{
    extern __shared__ float sm[];
    float* ubuf = sm;                       // [ROWS][TUU][FF]
    float* zbuf = ubuf + ROWS * TUU * FF;   // [ROWS][ZZ]
    float* hbuf = zbuf + ROWS * ZZ;         // [ROWS][HH]
    float* part = hbuf + ROWS * HH;         // [ROWS][4][64]
    float* te   = part + ROWS * HH;         // [64]
    float* tu   = te + 64;                  // [TUU]

    const int tid = threadIdx.x;
    const int b0  = blockIdx.x * ROWS;

    // ---- one-time loads ----
    for (int i = tid; i < TT;  i += NTHREADS) te[i] = te_g[i];
    for (int i = tid; i < TUU; i += NTHREADS) tu[i] = tu_g[i];
    for (int i = tid; i < ROWS * TUU * FF; i += NTHREADS) {
        int r = i / (TUU * FF);
        int o = i - r * (TUU * FF);
        ubuf[i] = u_g[(size_t)(b0 + r) * (TUU * FF) + o];
    }

    // W1 column j (packed over K pairs), persistent in registers
    const int j = tid;
    u64 w1p[ZZ / 2];
#pragma unroll
    for (int i = 0; i < ZZ / 2; ++i)
        w1p[i] = pack2(W1g[(2 * i) * HH + j], W1g[(2 * i + 1) * HH + j]);
    const float b1j = b1g[j];

    // W2 slice: p = k-quarter, dcol = output column (packed over K pairs)
    const int p    = tid >> 6;
    const int dcol = tid & 63;
    u64 w2p[32];
#pragma unroll
    for (int i = 0; i < 32; ++i)
        w2p[i] = pack2(W2g[(p * 64 + 2 * i) * DD + dcol],
                       W2g[(p * 64 + 2 * i + 1) * DD + dcol]);
    const float b2d = b2g[dcol];

    // Owner state: thread owns elements (r0,dcol) and (r0+4,dcol)
    const int r0 = tid >> 6;   // 0..3 ; second element row = r0+4
    float xc[2];
    float kk[2][6];
#pragma unroll
    for (int q = 0; q < 2; ++q) {
        int rr = r0 + 4 * q;
        xc[q] = x0g[(size_t)(b0 + rr) * DD + dcol];
        out[(size_t)(b0 + rr) * (TT * DD) + dcol] = xc[q];   // t index 0
    }
    __syncthreads();

    // Dopri5 tableau (fp32-rounded, matching jax f32 weak-type promotion)
    const float A21 = 0.2f;
    const float A31 = 0.075f,                    A32 = 0.225f;
    const float A41 = (float)( 44.0/45.0),       A42 = (float)(-56.0/15.0),
                A43 = (float)( 32.0/9.0);
    const float A51 = (float)( 19372.0/6561.0),  A52 = (float)(-25360.0/2187.0),
                A53 = (float)( 64448.0/6561.0),  A54 = (float)(-212.0/729.0);
    const float A61 = (float)( 9017.0/3168.0),   A62 = (float)(-355.0/33.0),
                A63 = (float)( 46732.0/5247.0),  A64 = (float)( 49.0/176.0),
                A65 = (float)(-5103.0/18656.0);
    const float B1  = (float)( 35.0/384.0),      B3  = (float)(500.0/1113.0),
                B4  = (float)(125.0/192.0),      B5  = (float)(-2187.0/6784.0),
                B6  = (float)( 11.0/84.0);
    const float CST[6] = {0.0f, 0.2f, 0.3f, 0.8f, (float)(8.0/9.0), 1.0f};

    for (int ci = 0; ci < TT - 1; ++ci) {
        const float tc0 = te[ci];
        const float dtc = te[ci + 1] - tc0;
        const float dt  = dtc * 0.25f;
        for (int s = 0; s < NSUB; ++s) {
            const float tsub = tc0 + dtc * ((float)s * 0.25f);

            for (int stage = 0; stage < 6; ++stage) {
                // ---- owner: reduce previous stage's partials into kk ----
                if (stage > 0) {
#pragma unroll
                    for (int q = 0; q < 2; ++q) {
                        int rr = r0 + 4 * q;
                        const float* pr = part + rr * HH + dcol;
                        kk[q][stage - 1] = pr[0] + pr[64] + pr[128] + pr[192] + b2d;
                    }
                }
                // ---- build z: x-part ----
#pragma unroll
                for (int q = 0; q < 2; ++q) {
                    int rr = r0 + 4 * q;
                    float xs;
                    switch (stage) {
                    case 0: xs = xc[q]; break;
                    case 1: xs = xc[q] + dt * (A21 * kk[q][0]); break;
                    case 2: xs = xc[q] + dt * (A31 * kk[q][0] + A32 * kk[q][1]); break;
                    case 3: xs = xc[q] + dt * (A41 * kk[q][0] + A42 * kk[q][1]
                                             + A43 * kk[q][2]); break;
                    case 4: xs = xc[q] + dt * (A51 * kk[q][0] + A52 * kk[q][1]
                                             + A53 * kk[q][2] + A54 * kk[q][3]); break;
                    default: xs = xc[q] + dt * (A61 * kk[q][0] + A62 * kk[q][1]
                                              + A63 * kk[q][2] + A64 * kk[q][3]
                                              + A65 * kk[q][4]); break;
                    }
                    zbuf[rr * ZZ + dcol] = xs;
                }
                // ---- build z: u-part (exact searchsorted semantics) ----
                if (tid < ROWS * FF) {
                    float tst = tsub + CST[stage] * dt;
                    int idx = (int)floorf(tst * (float)(TUU - 1));
                    idx = max(0, min(TUU - 2, idx));
                    while (idx > 0 && tu[idx] > tst) --idx;
                    while (idx < TUU - 2 && tu[idx + 1] <= tst) ++idx;
                    float t0v = tu[idx], t1v = tu[idx + 1];
                    float w = (tst - t0v) / (t1v - t0v);
                    int rr = tid / FF, ff = tid - rr * FF;
                    float u0v = ubuf[rr * (TUU * FF) + idx * FF + ff];
                    float u1v = ubuf[rr * (TUU * FF) + (idx + 1) * FF + ff];
                    zbuf[rr * ZZ + DD + ff] = u0v + w * (u1v - u0v);
                }
                __syncthreads();

                // ---- layer 1: h[r][j] = tanh(z[r] . W1[:,j] + b1[j]) ----
                for (int rr = 0; rr < ROWS; ++rr) {
                    const ulonglong2* zr =
                        reinterpret_cast<const ulonglong2*>(zbuf + rr * ZZ);
                    u64 a0 = 0ull, a1 = 0ull;
#pragma unroll
                    for (int i = 0; i < ZZ / 4; ++i) {   // 18 LDS.128, 36 FMA2
                        ulonglong2 zz = zr[i];
                        a0 = fma2(zz.x, w1p[2 * i],     a0);
                        a1 = fma2(zz.y, w1p[2 * i + 1], a1);
                    }
                    float2 f0 = unpack2(a0), f1 = unpack2(a1);
                    hbuf[rr * HH + j] = fast_tanh(f0.x + f0.y + f1.x + f1.y + b1j);
                }
                __syncthreads();

                // ---- layer 2 partials: quarter-K dot into part ----
                for (int rr = 0; rr < ROWS; ++rr) {
                    const ulonglong2* hr =
                        reinterpret_cast<const ulonglong2*>(hbuf + rr * HH + p * 64);
                    u64 a0 = 0ull, a1 = 0ull;
#pragma unroll
                    for (int i = 0; i < 16; ++i) {       // 16 LDS.128, 32 FMA2
                        ulonglong2 hh = hr[i];
                        a0 = fma2(hh.x, w2p[2 * i],     a0);
                        a1 = fma2(hh.y, w2p[2 * i + 1], a1);
                    }
                    float2 f0 = unpack2(a0), f1 = unpack2(a1);
                    part[rr * HH + p * 64 + dcol] = f0.x + f0.y + f1.x + f1.y;
                }
                __syncthreads();
            } // stages

            // ---- final combine: k6 from part, advance x ----
#pragma unroll
            for (int q = 0; q < 2; ++q) {
                int rr = r0 + 4 * q;
                const float* pr = part + rr * HH + dcol;
                float k6 = pr[0] + pr[64] + pr[128] + pr[192] + b2d;
                float xn = xc[q] + dt * (B1 * kk[q][0] + B3 * kk[q][2]
                                       + B4 * kk[q][3] + B5 * kk[q][4] + B6 * k6);
                xc[q] = xn;
                if (s == NSUB - 1)
                    out[(size_t)(b0 + rr) * (TT * DD) + (ci + 1) * DD + dcol] = xn;
            }
            // No extra barrier needed: next stage-0 writes to zbuf/part happen
            // only after two more __syncthreads inside the stage loop.
        }
    }
}

extern "C" void kernel_launch(void* const* d_in, const int* in_sizes, int n_in,
                              void* d_out, int out_size) {
    const float* x0 = (const float*)d_in[0];
    const float* te = (const float*)d_in[1];
    const float* tu = (const float*)d_in[2];
    const float* ub = (const float*)d_in[3];
    const float* W1 = (const float*)d_in[4];
    const float* b1 = (const float*)d_in[5];
    const float* W2 = (const float*)d_in[6];
    const float* b2 = (const float*)d_in[7];
    float* out = (float*)d_out;

    const int smem_bytes = SMEM_FLOATS * (int)sizeof(float);   // 52224 B
    cudaFuncSetAttribute(node_kernel,
                         cudaFuncAttributeMaxDynamicSharedMemorySize, smem_bytes);
    node_kernel<<<CTAS, NTHREADS, smem_bytes>>>(x0, te, tu, ub, W1, b1, W2, b2, out);
}

// round 2
// speedup vs baseline: 1.1372x; 1.1372x over previous
#include <cuda_runtime.h>

#define BB 1024
#define DD 64
#define FF 8
#define ZZ 72          // D + F
#define HH 256
#define TT 50
#define TUU 128
#define NSUB 4
#define ROWS 8         // batch rows per CTA
#define CTAS (BB/ROWS) // 128
#define NT 512

typedef unsigned long long u64;

__device__ __forceinline__ u64 fma2(u64 a, u64 b, u64 c) {
    u64 d;
    asm("fma.rn.f32x2 %0, %1, %2, %3;" : "=l"(d) : "l"(a), "l"(b), "l"(c));
    return d;
}
__device__ __forceinline__ u64 pack2(float lo, float hi) {
    u64 d;
    asm("mov.b64 %0, {%1, %2};" : "=l"(d) : "f"(lo), "f"(hi));
    return d;
}
__device__ __forceinline__ float2 unpack2(u64 v) {
    float lo, hi;
    asm("mov.b64 {%0, %1}, %2;" : "=f"(lo), "=f"(hi) : "l"(v));
    return make_float2(lo, hi);
}

// tanh(x) = 1 - 2/(exp(2x)+1) via ex2.approx + rcp.approx, abs err ~1e-6.
__device__ __forceinline__ float fast_tanh(float x) {
    float e, r;
    asm("ex2.approx.f32 %0, %1;" : "=f"(e) : "f"(x * 2.8853900817779268f));
    asm("rcp.approx.f32 %0, %1;" : "=f"(r) : "f"(e + 1.0f));
    return fmaf(-2.0f, r, 1.0f);
}

// SMEM floats:
//   ubuf : 8*128*8 = 8192
//   zbuf : 8*72    = 576
//   hbuf : 8*256   = 2048
//   pbuf : 8*512   = 4096   (layer1 partials ALIASED with layer2 partials;
//                            live ranges separated by barriers)
//   te   : 64, tu : 128
#define SMEM_FLOATS (8192 + 576 + 2048 + 4096 + 64 + 128)

__global__ void __launch_bounds__(NT, 1)
node_kernel(const float* __restrict__ x0g, const float* __restrict__ te_g,
            const float* __restrict__ tu_g, const float* __restrict__ u_g,
            const float* __restrict__ W1g, const float* __restrict__ b1g,
            const float* __restrict__ W2g, const float* __restrict__ b2g,
            float* __restrict__ out)
{
    extern __shared__ float sm[];
    float* ubuf = sm;                  // [ROWS][TUU][FF]
    float* zbuf = ubuf + 8192;         // [ROWS][ZZ]
    float* hbuf = zbuf + ROWS * ZZ;    // [ROWS][HH]
    float* pbuf = hbuf + ROWS * HH;    // [ROWS][512]
    float* te   = pbuf + ROWS * 512;   // [64]
    float* tu   = te + 64;             // [TUU]

    const int tid = threadIdx.x;
    const int b0  = blockIdx.x * ROWS;

    // ---- one-time loads ----
    for (int i = tid; i < TT;  i += NT) te[i] = te_g[i];
    for (int i = tid; i < TUU; i += NT) tu[i] = tu_g[i];
    for (int i = tid; i < ROWS * TUU * FF; i += NT) {
        int r = i / (TUU * FF);
        int o = i - r * (TUU * FF);
        ubuf[i] = u_g[(size_t)(b0 + r) * (TUU * FF) + o];
    }

    // Layer-1 weights: thread (half, j) owns column j, K-half [half*36, half*36+36)
    const int half = tid >> 8;         // 0..1
    const int j    = tid & 255;
    u64 w1p[18];
#pragma unroll
    for (int i = 0; i < 18; ++i)
        w1p[i] = pack2(W1g[(half * 36 + 2 * i) * HH + j],
                       W1g[(half * 36 + 2 * i + 1) * HH + j]);
    const float b1j = (half == 0) ? b1g[j] : 0.0f;  // bias folded into half-0 partial

    // Layer-2 weights: thread (pg, dcol) owns column dcol, K-slice [pg*32, pg*32+32)
    const int pg   = tid >> 6;         // 0..7
    const int dcol = tid & 63;
    u64 w2p[16];
#pragma unroll
    for (int i = 0; i < 16; ++i)
        w2p[i] = pack2(W2g[(pg * 32 + 2 * i) * DD + dcol],
                       W2g[(pg * 32 + 2 * i + 1) * DD + dcol]);
    const float b2d = b2g[dcol];

    // Owner: thread owns state element (orr, dcol); orr == pg
    const int orr = pg;
    float xc = x0g[(size_t)(b0 + orr) * DD + dcol];
    out[(size_t)(b0 + orr) * (TT * DD) + dcol] = xc;   // t index 0
    float kk[6];
    __syncthreads();

    // Dopri5 tableau (fp32-rounded)
    const float A21 = 0.2f;
    const float A31 = 0.075f,                    A32 = 0.225f;
    const float A41 = (float)( 44.0/45.0),       A42 = (float)(-56.0/15.0),
                A43 = (float)( 32.0/9.0);
    const float A51 = (float)( 19372.0/6561.0),  A52 = (float)(-25360.0/2187.0),
                A53 = (float)( 64448.0/6561.0),  A54 = (float)(-212.0/729.0);
    const float A61 = (float)( 9017.0/3168.0),   A62 = (float)(-355.0/33.0),
                A63 = (float)( 46732.0/5247.0),  A64 = (float)( 49.0/176.0),
                A65 = (float)(-5103.0/18656.0);
    const float B1  = (float)( 35.0/384.0),      B3  = (float)(500.0/1113.0),
                B4  = (float)(125.0/192.0),      B5  = (float)(-2187.0/6784.0),
                B6  = (float)( 11.0/84.0);
    const float CST[6] = {0.0f, 0.2f, 0.3f, 0.8f, (float)(8.0/9.0), 1.0f};

    for (int ci = 0; ci < TT - 1; ++ci) {
        const float tc0 = te[ci];
        const float dtc = te[ci + 1] - tc0;
        const float dt  = dtc * 0.25f;
        for (int s = 0; s < NSUB; ++s) {
            const float tsub = tc0 + dtc * ((float)s * 0.25f);

#pragma unroll
            for (int stage = 0; stage < 6; ++stage) {
                // ---- owner: reduce previous stage's layer-2 partials ----
                if (stage > 0) {
                    const float* pr = pbuf + orr * 512 + dcol;
                    float a = pr[0] + pr[64];
                    float b = pr[128] + pr[192];
                    float c = pr[256] + pr[320];
                    float d = pr[384] + pr[448];
                    kk[stage - 1] = (a + b) + (c + d) + b2d;
                }
                // ---- owner: build z x-part (1 element per thread) ----
                {
                    float xs;
                    switch (stage) {
                    case 0: xs = xc; break;
                    case 1: xs = xc + dt * (A21 * kk[0]); break;
                    case 2: xs = xc + dt * (A31 * kk[0] + A32 * kk[1]); break;
                    case 3: xs = xc + dt * (A41 * kk[0] + A42 * kk[1]
                                          + A43 * kk[2]); break;
                    case 4: xs = xc + dt * (A51 * kk[0] + A52 * kk[1]
                                          + A53 * kk[2] + A54 * kk[3]); break;
                    default: xs = xc + dt * (A61 * kk[0] + A62 * kk[1]
                                           + A63 * kk[2] + A64 * kk[3]
                                           + A65 * kk[4]); break;
                    }
                    zbuf[orr * ZZ + dcol] = xs;
                }
                // ---- z u-part (exact searchsorted; t_u uniform so guess exact) ----
                if (tid < ROWS * FF) {
                    float tst = tsub + CST[stage] * dt;
                    int idx = (int)floorf(tst * (float)(TUU - 1));
                    idx = max(0, min(TUU - 2, idx));
                    while (idx > 0 && tu[idx] > tst) --idx;
                    while (idx < TUU - 2 && tu[idx + 1] <= tst) ++idx;
                    float t0v = tu[idx], t1v = tu[idx + 1];
                    float w = (tst - t0v) / (t1v - t0v);
                    int rr = tid >> 3, ff = tid & 7;
                    float u0v = ubuf[rr * (TUU * FF) + idx * FF + ff];
                    float u1v = ubuf[rr * (TUU * FF) + (idx + 1) * FF + ff];
                    zbuf[rr * ZZ + DD + ff] = u0v + w * (u1v - u0v);
                }
                __syncthreads();

                // ---- layer 1 partials: half-K dot per column ----
#pragma unroll
                for (int rr = 0; rr < ROWS; ++rr) {
                    const ulonglong2* zr = reinterpret_cast<const ulonglong2*>(
                        zbuf + rr * ZZ + half * 36);
                    u64 a0 = 0ull, a1 = 0ull;
#pragma unroll
                    for (int i = 0; i < 9; ++i) {        // 9 LDS.128, 18 FMA2
                        ulonglong2 zz = zr[i];
                        a0 = fma2(zz.x, w1p[2 * i],     a0);
                        a1 = fma2(zz.y, w1p[2 * i + 1], a1);
                    }
                    float2 f0 = unpack2(a0), f1 = unpack2(a1);
                    pbuf[rr * 512 + half * 256 + j] =
                        (f0.x + f0.y) + (f1.x + f1.y) + b1j;
                }
                __syncthreads();

                // ---- combine halves + tanh -> hbuf (4 outputs per thread) ----
#pragma unroll
                for (int c = 0; c < 4; ++c) {
                    int o  = c * NT + tid;               // 0..2047
                    int rr = o >> 8;
                    int jc = o & 255;
                    float v = pbuf[rr * 512 + jc] + pbuf[rr * 512 + 256 + jc];
                    hbuf[o] = fast_tanh(v);
                }
                __syncthreads();

                // ---- layer 2 partials: 32-K slice dot per column ----
#pragma unroll
                for (int rr = 0; rr < ROWS; ++rr) {
                    const ulonglong2* hr = reinterpret_cast<const ulonglong2*>(
                        hbuf + rr * HH + pg * 32);
                    u64 a0 = 0ull, a1 = 0ull;
#pragma unroll
                    for (int i = 0; i < 8; ++i) {        // 8 LDS.128, 16 FMA2
                        ulonglong2 hh = hr[i];
                        a0 = fma2(hh.x, w2p[2 * i],     a0);
                        a1 = fma2(hh.y, w2p[2 * i + 1], a1);
                    }
                    float2 f0 = unpack2(a0), f1 = unpack2(a1);
                    pbuf[rr * 512 + tid] = (f0.x + f0.y) + (f1.x + f1.y);
                }
                __syncthreads();
            } // stages

            // ---- final: k6 from pbuf, advance x ----
            {
                const float* pr = pbuf + orr * 512 + dcol;
                float a = pr[0] + pr[64];
                float b = pr[128] + pr[192];
                float c = pr[256] + pr[320];
                float d = pr[384] + pr[448];
                float k6 = (a + b) + (c + d) + b2d;
                float xn = xc + dt * (B1 * kk[0] + B3 * kk[2]
                                    + B4 * kk[3] + B5 * kk[4] + B6 * k6);
                xc = xn;
                if (s == NSUB - 1)
                    out[(size_t)(b0 + orr) * (TT * DD) + (ci + 1) * DD + dcol] = xn;
            }
            // Safe without an extra barrier: the next stage's pbuf writes
            // happen only after the z-phase __syncthreads.
        }
    }
}

extern "C" void kernel_launch(void* const* d_in, const int* in_sizes, int n_in,
                              void* d_out, int out_size) {
    const float* x0 = (const float*)d_in[0];
    const float* te = (const float*)d_in[1];
    const float* tu = (const float*)d_in[2];
    const float* ub = (const float*)d_in[3];
    const float* W1 = (const float*)d_in[4];
    const float* b1 = (const float*)d_in[5];
    const float* W2 = (const float*)d_in[6];
    const float* b2 = (const float*)d_in[7];
    float* out = (float*)d_out;

    const int smem_bytes = SMEM_FLOATS * (int)sizeof(float);   // 60416 B
    cudaFuncSetAttribute(node_kernel,
                         cudaFuncAttributeMaxDynamicSharedMemorySize, smem_bytes);
    node_kernel<<<CTAS, NT, smem_bytes>>>(x0, te, tu, ub, W1, b1, W2, b2, out);
}